// round 1
// baseline (speedup 1.0000x reference)
#include <cuda_runtime.h>

#define TOTAL_QUBITS 24
#define DIM (1u << TOTAL_QUBITS)
#define BATCH 4

// Each thread processes 4 consecutive "rest" indices (float4 vectorized) for
// one batch. rest-index space is 2^22 per batch (24 qubits minus the 2 gate
// qubits). Gate bit positions come from device scalars q0,q1 at runtime:
// axis q in the reference's tensor layout == linear-index bit (23 - q).
__global__ __launch_bounds__(256)
void quantum_gate_kernel(const float* __restrict__ state,
                         const float* __restrict__ matrix,
                         const int* __restrict__ q0p,
                         const int* __restrict__ q1p,
                         float* __restrict__ out)
{
    const int q0 = q0p[0];
    const int q1 = q1p[0];
    const int bq0 = TOTAL_QUBITS - 1 - q0;   // bit whose value is the HIGH bit of g
    const int bq1 = TOTAL_QUBITS - 1 - q1;   // bit whose value is the LOW  bit of g
    const int blo = bq0 < bq1 ? bq0 : bq1;
    const int bhi = bq0 < bq1 ? bq1 : bq0;

    // 4x4 gate matrix, row-major: out_g = sum_k m[g*4+k] * s_k
    float m[16];
#pragma unroll
    for (int i = 0; i < 16; i++) m[i] = __ldg(matrix + i);

    const unsigned vec_per_batch = DIM >> 4;               // 2^20 float4-groups per batch
    unsigned t = blockIdx.x * blockDim.x + threadIdx.x;
    unsigned b  = t >> 20;                                 // batch (BATCH * 2^20 threads total)
    unsigned rv = t & (vec_per_batch - 1);
    if (b >= BATCH) return;

    const size_t boff = (size_t)b << TOTAL_QUBITS;
    const unsigned off1 = 1u << bq1;                       // toggles low bit of g
    const unsigned off2 = 1u << bq0;                       // toggles high bit of g

    if (blo >= 2) {
        // ---- vectorized path (the actual case: bits 13 and 20) ----
        unsigned r    = rv << 2;                           // rest index, multiple of 4
        unsigned low  = r & ((1u << blo) - 1);
        unsigned mid  = (r >> blo) & ((1u << (bhi - 1 - blo)) - 1);
        unsigned high = r >> (bhi - 1);
        unsigned base = low | (mid << (blo + 1)) | (high << (bhi + 1));

        const float* sp = state + boff;
        float*       op = out   + boff;

        float4 s0 = *reinterpret_cast<const float4*>(sp + base);
        float4 s1 = *reinterpret_cast<const float4*>(sp + base + off1);
        float4 s2 = *reinterpret_cast<const float4*>(sp + base + off2);
        float4 s3 = *reinterpret_cast<const float4*>(sp + base + off1 + off2);

        float4 o0, o1, o2, o3;
#define APPLY(comp)                                                              \
        o0.comp = m[0]*s0.comp + m[1]*s1.comp + m[2]*s2.comp + m[3]*s3.comp;     \
        o1.comp = m[4]*s0.comp + m[5]*s1.comp + m[6]*s2.comp + m[7]*s3.comp;     \
        o2.comp = m[8]*s0.comp + m[9]*s1.comp + m[10]*s2.comp + m[11]*s3.comp;   \
        o3.comp = m[12]*s0.comp + m[13]*s1.comp + m[14]*s2.comp + m[15]*s3.comp;
        APPLY(x) APPLY(y) APPLY(z) APPLY(w)
#undef APPLY

        *reinterpret_cast<float4*>(op + base)               = o0;
        *reinterpret_cast<float4*>(op + base + off1)        = o1;
        *reinterpret_cast<float4*>(op + base + off2)        = o2;
        *reinterpret_cast<float4*>(op + base + off1 + off2) = o3;
    } else {
        // ---- scalar fallback (gate bit in the low 2 index bits) ----
        const float* sp = state + boff;
        float*       op = out   + boff;
#pragma unroll
        for (int i = 0; i < 4; i++) {
            unsigned r    = (rv << 2) + i;
            unsigned low  = r & ((1u << blo) - 1);
            unsigned midmask = (bhi - 1 - blo) >= 32 ? 0xFFFFFFFFu : ((1u << (bhi - 1 - blo)) - 1);
            unsigned mid  = (r >> blo) & midmask;
            unsigned high = r >> (bhi - 1);
            unsigned base = low | (mid << (blo + 1)) | (high << (bhi + 1));

            float s0 = sp[base];
            float s1 = sp[base + off1];
            float s2 = sp[base + off2];
            float s3 = sp[base + off1 + off2];

            op[base]               = m[0]*s0  + m[1]*s1  + m[2]*s2  + m[3]*s3;
            op[base + off1]        = m[4]*s0  + m[5]*s1  + m[6]*s2  + m[7]*s3;
            op[base + off2]        = m[8]*s0  + m[9]*s1  + m[10]*s2 + m[11]*s3;
            op[base + off1 + off2] = m[12]*s0 + m[13]*s1 + m[14]*s2 + m[15]*s3;
        }
    }
}

extern "C" void kernel_launch(void* const* d_in, const int* in_sizes, int n_in,
                              void* d_out, int out_size)
{
    const float* state  = (const float*)d_in[0];
    const float* matrix = (const float*)d_in[1];
    const int*   q0     = (const int*)d_in[2];
    const int*   q1     = (const int*)d_in[3];
    float*       out    = (float*)d_out;

    // BATCH * 2^20 threads, each handling one float4-group of 4 rest indices
    const unsigned total_threads = BATCH * (DIM >> 4);
    const unsigned block = 256;
    const unsigned grid  = (total_threads + block - 1) / block;
    quantum_gate_kernel<<<grid, block>>>(state, matrix, q0, q1, out);
}

// round 2
// speedup vs baseline: 1.0082x; 1.0082x over previous
#include <cuda_runtime.h>

#define TOTAL_QUBITS 24
#define DIM (1u << TOTAL_QUBITS)
#define BATCH 4
#define GROUPS_TOTAL (BATCH * (DIM >> 4))   // 4 * 2^20 float4-groups
#define GROUPS_PER_THREAD 2

// 2-qubit gate on batched 2^24 statevector. Memory-bound streaming kernel:
// 256MB read + 256MB write, zero reuse. Strategy: 128-bit LD/ST on all 8
// streams, evict-first cache hints (__ldcs/__stcs) since data is use-once,
// 2 groups per thread (grid-split, preserving warp coalescing) for deeper MLP.
__global__ __launch_bounds__(256)
void quantum_gate_kernel(const float* __restrict__ state,
                         const float* __restrict__ matrix,
                         const int* __restrict__ q0p,
                         const int* __restrict__ q1p,
                         float* __restrict__ out)
{
    const int q0 = q0p[0];
    const int q1 = q1p[0];
    const int bq0 = TOTAL_QUBITS - 1 - q0;   // linear-index bit = HIGH bit of g
    const int bq1 = TOTAL_QUBITS - 1 - q1;   // linear-index bit = LOW  bit of g
    const int blo = bq0 < bq1 ? bq0 : bq1;
    const int bhi = bq0 < bq1 ? bq1 : bq0;

    float m[16];
#pragma unroll
    for (int i = 0; i < 16; i++) m[i] = __ldg(matrix + i);

    const unsigned off1 = 1u << bq1;
    const unsigned off2 = 1u << bq0;

    const unsigned t = blockIdx.x * blockDim.x + threadIdx.x;
    const unsigned half = GROUPS_TOTAL / GROUPS_PER_THREAD;   // 2^21
    if (t >= half) return;

    if (blo >= 2) {
        // ---- vectorized path (actual case: gate bits 13 and 20) ----
        // Precompute bases + pointers for both groups, then front-batch all
        // 8 LDG.128 before any FMA (maximize MLP).
        unsigned base_[GROUPS_PER_THREAD];
        const float* sp_[GROUPS_PER_THREAD];
        float*       op_[GROUPS_PER_THREAD];
#pragma unroll
        for (int j = 0; j < GROUPS_PER_THREAD; j++) {
            unsigned g  = t + j * half;                 // group id
            unsigned b  = g >> 20;                      // batch
            unsigned rv = g & ((1u << 20) - 1);
            unsigned r  = rv << 2;                      // rest index (mult of 4)
            unsigned low  = r & ((1u << blo) - 1);
            unsigned mid  = (r >> blo) & ((1u << (bhi - 1 - blo)) - 1);
            unsigned high = r >> (bhi - 1);
            base_[j] = low | (mid << (blo + 1)) | (high << (bhi + 1));
            size_t boff = (size_t)b << TOTAL_QUBITS;
            sp_[j] = state + boff;
            op_[j] = out   + boff;
        }

        float4 s0_[GROUPS_PER_THREAD], s1_[GROUPS_PER_THREAD],
               s2_[GROUPS_PER_THREAD], s3_[GROUPS_PER_THREAD];
#pragma unroll
        for (int j = 0; j < GROUPS_PER_THREAD; j++) {
            const float4* p = reinterpret_cast<const float4*>(sp_[j] + base_[j]);
            const float4* p1 = reinterpret_cast<const float4*>(sp_[j] + base_[j] + off1);
            const float4* p2 = reinterpret_cast<const float4*>(sp_[j] + base_[j] + off2);
            const float4* p3 = reinterpret_cast<const float4*>(sp_[j] + base_[j] + off1 + off2);
            s0_[j] = __ldcs(p);
            s1_[j] = __ldcs(p1);
            s2_[j] = __ldcs(p2);
            s3_[j] = __ldcs(p3);
        }

#pragma unroll
        for (int j = 0; j < GROUPS_PER_THREAD; j++) {
            float4 s0 = s0_[j], s1 = s1_[j], s2 = s2_[j], s3 = s3_[j];
            float4 o0, o1, o2, o3;
#define APPLY(comp)                                                              \
            o0.comp = m[0]*s0.comp + m[1]*s1.comp + m[2]*s2.comp + m[3]*s3.comp; \
            o1.comp = m[4]*s0.comp + m[5]*s1.comp + m[6]*s2.comp + m[7]*s3.comp; \
            o2.comp = m[8]*s0.comp + m[9]*s1.comp + m[10]*s2.comp + m[11]*s3.comp; \
            o3.comp = m[12]*s0.comp + m[13]*s1.comp + m[14]*s2.comp + m[15]*s3.comp;
            APPLY(x) APPLY(y) APPLY(z) APPLY(w)
#undef APPLY
            __stcs(reinterpret_cast<float4*>(op_[j] + base_[j]),               o0);
            __stcs(reinterpret_cast<float4*>(op_[j] + base_[j] + off1),        o1);
            __stcs(reinterpret_cast<float4*>(op_[j] + base_[j] + off2),        o2);
            __stcs(reinterpret_cast<float4*>(op_[j] + base_[j] + off1 + off2), o3);
        }
    } else {
        // ---- scalar fallback (gate bit in low 2 index bits) ----
#pragma unroll
        for (int j = 0; j < GROUPS_PER_THREAD; j++) {
            unsigned g  = t + j * half;
            unsigned b  = g >> 20;
            unsigned rv = g & ((1u << 20) - 1);
            size_t boff = (size_t)b << TOTAL_QUBITS;
            const float* sp = state + boff;
            float*       op = out   + boff;
#pragma unroll
            for (int i = 0; i < 4; i++) {
                unsigned r    = (rv << 2) + i;
                unsigned low  = r & ((1u << blo) - 1);
                unsigned midmask = (bhi - 1 - blo) >= 32 ? 0xFFFFFFFFu
                                                         : ((1u << (bhi - 1 - blo)) - 1);
                unsigned mid  = (r >> blo) & midmask;
                unsigned high = r >> (bhi - 1);
                unsigned base = low | (mid << (blo + 1)) | (high << (bhi + 1));

                float s0 = sp[base];
                float s1 = sp[base + off1];
                float s2 = sp[base + off2];
                float s3 = sp[base + off1 + off2];

                op[base]               = m[0]*s0  + m[1]*s1  + m[2]*s2  + m[3]*s3;
                op[base + off1]        = m[4]*s0  + m[5]*s1  + m[6]*s2  + m[7]*s3;
                op[base + off2]        = m[8]*s0  + m[9]*s1  + m[10]*s2 + m[11]*s3;
                op[base + off1 + off2] = m[12]*s0 + m[13]*s1 + m[14]*s2 + m[15]*s3;
            }
        }
    }
}

extern "C" void kernel_launch(void* const* d_in, const int* in_sizes, int n_in,
                              void* d_out, int out_size)
{
    const float* state  = (const float*)d_in[0];
    const float* matrix = (const float*)d_in[1];
    const int*   q0     = (const int*)d_in[2];
    const int*   q1     = (const int*)d_in[3];
    float*       out    = (float*)d_out;

    const unsigned total_threads = GROUPS_TOTAL / GROUPS_PER_THREAD;  // 2^21
    const unsigned block = 256;
    const unsigned grid  = (total_threads + block - 1) / block;       // 8192
    quantum_gate_kernel<<<grid, block>>>(state, matrix, q0, q1, out);
}

// round 3
// speedup vs baseline: 1.0094x; 1.0012x over previous
#include <cuda_runtime.h>

#define TOTAL_QUBITS 24
#define DIM (1u << TOTAL_QUBITS)
#define BATCH 4

// 2-qubit gate on batched 2^24 statevector. Pure streaming: 256MB read +
// 256MB write, zero reuse. R1 shape (1 float4-group/thread, low regs, high
// occupancy) + evict-first cache hints on all 8 streams.
__global__ __launch_bounds__(256)
void quantum_gate_kernel(const float* __restrict__ state,
                         const float* __restrict__ matrix,
                         const int* __restrict__ q0p,
                         const int* __restrict__ q1p,
                         float* __restrict__ out)
{
    const int q0 = q0p[0];
    const int q1 = q1p[0];
    const int bq0 = TOTAL_QUBITS - 1 - q0;   // linear-index bit = HIGH bit of g
    const int bq1 = TOTAL_QUBITS - 1 - q1;   // linear-index bit = LOW  bit of g
    const int blo = bq0 < bq1 ? bq0 : bq1;
    const int bhi = bq0 < bq1 ? bq1 : bq0;

    float m[16];
#pragma unroll
    for (int i = 0; i < 16; i++) m[i] = __ldg(matrix + i);

    const unsigned vec_per_batch = DIM >> 4;               // 2^20 groups per batch
    unsigned t = blockIdx.x * blockDim.x + threadIdx.x;
    unsigned b  = t >> 20;
    unsigned rv = t & (vec_per_batch - 1);
    if (b >= BATCH) return;

    const size_t boff = (size_t)b << TOTAL_QUBITS;
    const unsigned off1 = 1u << bq1;                       // toggles low bit of g
    const unsigned off2 = 1u << bq0;                       // toggles high bit of g

    if (blo >= 2) {
        // ---- vectorized path (actual case: gate bits 13 and 20) ----
        unsigned r    = rv << 2;
        unsigned low  = r & ((1u << blo) - 1);
        unsigned mid  = (r >> blo) & ((1u << (bhi - 1 - blo)) - 1);
        unsigned high = r >> (bhi - 1);
        unsigned base = low | (mid << (blo + 1)) | (high << (bhi + 1));

        const float* sp = state + boff;
        float*       op = out   + boff;

        float4 s0 = __ldcs(reinterpret_cast<const float4*>(sp + base));
        float4 s1 = __ldcs(reinterpret_cast<const float4*>(sp + base + off1));
        float4 s2 = __ldcs(reinterpret_cast<const float4*>(sp + base + off2));
        float4 s3 = __ldcs(reinterpret_cast<const float4*>(sp + base + off1 + off2));

        float4 o0, o1, o2, o3;
#define APPLY(comp)                                                              \
        o0.comp = m[0]*s0.comp + m[1]*s1.comp + m[2]*s2.comp + m[3]*s3.comp;     \
        o1.comp = m[4]*s0.comp + m[5]*s1.comp + m[6]*s2.comp + m[7]*s3.comp;     \
        o2.comp = m[8]*s0.comp + m[9]*s1.comp + m[10]*s2.comp + m[11]*s3.comp;   \
        o3.comp = m[12]*s0.comp + m[13]*s1.comp + m[14]*s2.comp + m[15]*s3.comp;
        APPLY(x) APPLY(y) APPLY(z) APPLY(w)
#undef APPLY

        __stcs(reinterpret_cast<float4*>(op + base),               o0);
        __stcs(reinterpret_cast<float4*>(op + base + off1),        o1);
        __stcs(reinterpret_cast<float4*>(op + base + off2),        o2);
        __stcs(reinterpret_cast<float4*>(op + base + off1 + off2), o3);
    } else {
        // ---- scalar fallback (gate bit in low 2 index bits) ----
        const float* sp = state + boff;
        float*       op = out   + boff;
#pragma unroll
        for (int i = 0; i < 4; i++) {
            unsigned r    = (rv << 2) + i;
            unsigned low  = r & ((1u << blo) - 1);
            unsigned midmask = (bhi - 1 - blo) >= 32 ? 0xFFFFFFFFu
                                                     : ((1u << (bhi - 1 - blo)) - 1);
            unsigned mid  = (r >> blo) & midmask;
            unsigned high = r >> (bhi - 1);
            unsigned base = low | (mid << (blo + 1)) | (high << (bhi + 1));

            float s0 = sp[base];
            float s1 = sp[base + off1];
            float s2 = sp[base + off2];
            float s3 = sp[base + off1 + off2];

            op[base]               = m[0]*s0  + m[1]*s1  + m[2]*s2  + m[3]*s3;
            op[base + off1]        = m[4]*s0  + m[5]*s1  + m[6]*s2  + m[7]*s3;
            op[base + off2]        = m[8]*s0  + m[9]*s1  + m[10]*s2 + m[11]*s3;
            op[base + off1 + off2] = m[12]*s0 + m[13]*s1 + m[14]*s2 + m[15]*s3;
        }
    }
}

extern "C" void kernel_launch(void* const* d_in, const int* in_sizes, int n_in,
                              void* d_out, int out_size)
{
    const float* state  = (const float*)d_in[0];
    const float* matrix = (const float*)d_in[1];
    const int*   q0     = (const int*)d_in[2];
    const int*   q1     = (const int*)d_in[3];
    float*       out    = (float*)d_out;

    const unsigned total_threads = BATCH * (DIM >> 4);     // 2^22
    const unsigned block = 256;
    const unsigned grid  = (total_threads + block - 1) / block;
    quantum_gate_kernel<<<grid, block>>>(state, matrix, q0, q1, out);
}